// round 1
// baseline (speedup 1.0000x reference)
#include <cuda_runtime.h>
#include <math.h>

#define NN   10000
#define EE   320000
#define DIN  256
#define HIDN 128
#define DALL 256
#define MM   100000
#define PP   15000
#define NB   79                    // ceil(NN/128)
#define NTILES ((NB*(NB+1))/2)     // 3160 upper-tri tiles

// ---------------- static device scratch (no allocations allowed) ------------
__device__ float  g_sup[2][NN*HIDN];
__device__ int    g_off[2][NN+1];
__device__ int    g_cur[2][NN];
__device__ int    g_ssrc[2][EE];
__device__ float  g_sval[2][EE];
__device__ float  g_negs[NN];
__device__ double g_acc[3];        // [0]=loss_real  [1]=loss_pseudo  [2]=lc_sum

// ---------------- helpers ----------------------------------------------------
__device__ __forceinline__ int tri_off(int b) { return b*NB - (b*(b-1))/2; }

// ---------------- zero -------------------------------------------------------
__global__ void k_zero() {
    int i = blockIdx.x*blockDim.x + threadIdx.x;
    if (i < 2*(NN+1)) ((int*)g_off)[i] = 0;
    if (i < 3) g_acc[i] = 0.0;
}

// ---------------- CSR build: count ------------------------------------------
__global__ void k_count(const int* __restrict__ d0, const int* __restrict__ d1) {
    int i = blockIdx.x*blockDim.x + threadIdx.x;
    if (i < EE)            atomicAdd(&g_off[0][d0[i]+1], 1);
    else if (i < 2*EE)     atomicAdd(&g_off[1][d1[i-EE]+1], 1);
}

// ---------------- CSR build: scan (1 block, 512 threads) ---------------------
__global__ void k_scan() {
    __shared__ int part[512];
    int tid = threadIdx.x;
    const int TOT = NN+1;
    const int CH  = (TOT + 511)/512;   // 20
    for (int g = 0; g < 2; g++) {
        int s = tid*CH, e = min(s+CH, TOT);
        int sum = 0;
        for (int i = s; i < e; i++) sum += g_off[g][i];
        part[tid] = sum;
        __syncthreads();
        if (tid == 0) {
            int run = 0;
            for (int i = 0; i < 512; i++) { int v = part[i]; part[i] = run; run += v; }
        }
        __syncthreads();
        int run = part[tid];
        for (int i = s; i < e; i++) {
            run += g_off[g][i];
            g_off[g][i] = run;
            if (i < NN) g_cur[g][i] = run;
        }
        __syncthreads();
    }
}

// ---------------- CSR build: fill ---------------------------------------------
__global__ void k_fill(const int* __restrict__ s0, const int* __restrict__ d0,
                       const float* __restrict__ v0,
                       const int* __restrict__ s1, const int* __restrict__ d1,
                       const float* __restrict__ v1) {
    int i = blockIdx.x*blockDim.x + threadIdx.x;
    if (i < EE) {
        int p = atomicAdd(&g_cur[0][d0[i]], 1);
        g_ssrc[0][p] = s0[i]; g_sval[0][p] = v0[i];
    } else if (i < 2*EE) {
        int j = i - EE;
        int p = atomicAdd(&g_cur[1][d1[j]], 1);
        g_ssrc[1][p] = s1[j]; g_sval[1][p] = v1[j];
    }
}

// ---------------- sup = x @ W + b   (tiled 128x128, 8x8 microtile) -----------
__global__ __launch_bounds__(256)
void k_sup(const float* __restrict__ x0, const float* __restrict__ W0, const float* __restrict__ b0,
           const float* __restrict__ x1, const float* __restrict__ W1, const float* __restrict__ b1) {
    int g = blockIdx.z;
    const float* x = g ? x1 : x0;
    const float* W = g ? W1 : W0;
    const float* b = g ? b1 : b0;
    float* sup = g_sup[g];

    __shared__ float As[32][128];
    __shared__ float Bs[32][128];
    int tid = threadIdx.x;
    int tx = tid & 15, ty = tid >> 4;
    int rb = blockIdx.x * 128;

    float acc[8][8];
#pragma unroll
    for (int i = 0; i < 8; i++)
#pragma unroll
        for (int j = 0; j < 8; j++) acc[i][j] = 0.f;

    for (int kc = 0; kc < DIN; kc += 32) {
#pragma unroll
        for (int p = 0; p < 4; p++) {               // A transpose load
            int idx = p*256 + tid;
            int row = idx & 127;
            int k0  = (idx >> 7) * 4;
            int gr  = rb + row;
            float4 v = make_float4(0.f,0.f,0.f,0.f);
            if (gr < NN) v = *(const float4*)(x + (size_t)gr*DIN + kc + k0);
            As[k0+0][row] = v.x; As[k0+1][row] = v.y;
            As[k0+2][row] = v.z; As[k0+3][row] = v.w;
        }
#pragma unroll
        for (int p = 0; p < 4; p++) {               // W direct load
            int idx = p*256 + tid;
            int kk  = idx >> 5;
            int c4  = (idx & 31) * 4;
            float4 v = *(const float4*)(W + (size_t)(kc+kk)*HIDN + c4);
            *(float4*)&Bs[kk][c4] = v;
        }
        __syncthreads();
#pragma unroll
        for (int k = 0; k < 32; k++) {
            float4 a0 = *(float4*)&As[k][ty*4];
            float4 a1 = *(float4*)&As[k][64 + ty*4];
            float4 c0 = *(float4*)&Bs[k][tx*4];
            float4 c1 = *(float4*)&Bs[k][64 + tx*4];
            float a[8] = {a0.x,a0.y,a0.z,a0.w,a1.x,a1.y,a1.z,a1.w};
            float c[8] = {c0.x,c0.y,c0.z,c0.w,c1.x,c1.y,c1.z,c1.w};
#pragma unroll
            for (int i = 0; i < 8; i++)
#pragma unroll
                for (int j = 0; j < 8; j++) acc[i][j] = fmaf(a[i], c[j], acc[i][j]);
        }
        __syncthreads();
    }
    float4 bv0 = *(const float4*)(b + tx*4);
    float4 bv1 = *(const float4*)(b + 64 + tx*4);
    float bb[8] = {bv0.x,bv0.y,bv0.z,bv0.w,bv1.x,bv1.y,bv1.z,bv1.w};
#pragma unroll
    for (int i = 0; i < 8; i++) {
        int r  = (i < 4) ? (ty*4 + i) : (64 + ty*4 + (i-4));
        int gr = rb + r;
        if (gr < NN) {
            float4 o0 = make_float4(acc[i][0]+bb[0], acc[i][1]+bb[1],
                                    acc[i][2]+bb[2], acc[i][3]+bb[3]);
            float4 o1 = make_float4(acc[i][4]+bb[4], acc[i][5]+bb[5],
                                    acc[i][6]+bb[6], acc[i][7]+bb[7]);
            *(float4*)(sup + (size_t)gr*HIDN + tx*4)      = o0;
            *(float4*)(sup + (size_t)gr*HIDN + 64 + tx*4) = o1;
        }
    }
}

// ---------------- aggregate + l2norm -> x_all (d_out) ------------------------
__global__ __launch_bounds__(128)
void k_agg(float* __restrict__ out) {
    int n   = blockIdx.x;
    int g   = blockIdx.y;
    int tid = threadIdx.x;              // dim 0..127
    const float* sup = g_sup[g];
    __shared__ int   ss[128];
    __shared__ float sv[128];
    float acc = 0.f;
    int s0 = g_off[g][n], s1 = g_off[g][n+1];
    for (int base = s0; base < s1; base += 128) {
        int cnt = min(128, s1 - base);
        __syncthreads();
        if (tid < cnt) { ss[tid] = g_ssrc[g][base+tid]; sv[tid] = g_sval[g][base+tid]; }
        __syncthreads();
#pragma unroll 4
        for (int q = 0; q < cnt; q++)
            acc = fmaf(sup[(size_t)ss[q]*HIDN + tid], sv[q], acc);
    }
    float sq = acc*acc;
#pragma unroll
    for (int o = 16; o; o >>= 1) sq += __shfl_xor_sync(0xffffffffu, sq, o);
    __shared__ float wsum[4];
    if ((tid & 31) == 0) wsum[tid>>5] = sq;
    __syncthreads();
    float tot = wsum[0] + wsum[1] + wsum[2] + wsum[3];
    out[(size_t)n*DALL + g*HIDN + tid] = acc / sqrtf(tot);
}

// ---------------- neg_s[i] = cos(x_all[i], x_all[neg_row[i]]) ----------------
__global__ __launch_bounds__(128)
void k_negs(const float* __restrict__ xall, const int* __restrict__ negrow) {
    int w    = (blockIdx.x*blockDim.x + threadIdx.x) >> 5;
    int lane = threadIdx.x & 31;
    if (w >= NN) return;
    int j = negrow[w];
    const float4* a = (const float4*)(xall + (size_t)w*DALL);
    const float4* b = (const float4*)(xall + (size_t)j*DALL);
    float s = 0.f;
#pragma unroll
    for (int q = lane; q < 64; q += 32) {
        float4 av = a[q], bv = b[q];
        s += av.x*bv.x + av.y*bv.y + av.z*bv.z + av.w*bv.w;
    }
#pragma unroll
    for (int o = 16; o; o >>= 1) s += __shfl_xor_sync(0xffffffffu, s, o);
    if (lane == 0) g_negs[w] = 0.5f*s;   // norms are exactly sqrt(2)
}

// ---------------- lc (P pairs) ------------------------------------------------
__global__ __launch_bounds__(128)
void k_lc(const float* __restrict__ xall, const int* __restrict__ na,
          const int* __restrict__ nbv, const int* __restrict__ nl) {
    int w    = (blockIdx.x*blockDim.x + threadIdx.x) >> 5;
    int lane = threadIdx.x & 31;
    float term = 0.f;
    if (w < PP) {
        int ia = na[w], ib = nbv[w];
        const float4* a = (const float4*)(xall + (size_t)ia*DALL);
        const float4* b = (const float4*)(xall + (size_t)ib*DALL);
        float s = 0.f;
#pragma unroll
        for (int q = lane; q < 64; q += 32) {
            float4 av = a[q], bv = b[q];
            s += av.x*bv.x + av.y*bv.y + av.z*bv.z + av.w*bv.w;
        }
#pragma unroll
        for (int o = 16; o; o >>= 1) s += __shfl_xor_sync(0xffffffffu, s, o);
        if (lane == 0) {
            float sim = 0.5f*s;
            float z   = sim * 2.0f;                       // sim / TAU0, TAU0=0.5
            float ls  = (z >= 0.f) ? -log1pf(expf(-z)) : (z - log1pf(expf(z)));
            int   L   = nl[w];
            term = ldexpf(1.0f, -(L+1)) * ls;             // 0.5^(L+1), exact
        }
    }
    __shared__ float wr[4];
    if (lane == 0) wr[(threadIdx.x)>>5] = term;
    __syncthreads();
    if (threadIdx.x == 0) {
        double s = (double)wr[0] + wr[1] + wr[2] + wr[3];
        atomicAdd(&g_acc[2], s);
    }
}

// ---------------- loss_real (M pairs) -----------------------------------------
__global__ __launch_bounds__(128)
void k_real(const float* __restrict__ xall, const int* __restrict__ ts,
            const int* __restrict__ negidx) {
    int w    = (blockIdx.x*blockDim.x + threadIdx.x) >> 5;
    int lane = threadIdx.x & 31;
    float term = 0.f;
    if (w < MM) {
        int t0 = ts[2*w], t1 = ts[2*w+1], tn = negidx[w];
        const float4* rs = (const float4*)(xall + (size_t)t0*DALL);
        const float4* re = (const float4*)(xall + (size_t)t1*DALL);
        const float4* ng = (const float4*)(xall + (size_t)tn*DALL);
        float ps = 0.f, ns = 0.f;
#pragma unroll
        for (int q = lane; q < 64; q += 32) {
            float4 r = rs[q], e = re[q], n = ng[q];
            ps += r.x*e.x + r.y*e.y + r.z*e.z + r.w*e.w;
            ns += r.x*n.x + r.y*n.y + r.z*n.z + r.w*n.w;
        }
#pragma unroll
        for (int o = 16; o; o >>= 1) {
            ps += __shfl_xor_sync(0xffffffffu, ps, o);
            ns += __shfl_xor_sync(0xffffffffu, ns, o);
        }
        if (lane == 0) {
            float pos = 0.5f*ps, neg = 0.5f*ns;
            float u = (pos - 0.1f) * (1.0f/0.9f);
            term = (u*u) * log1pf(expf(neg - pos));
        }
    }
    __shared__ float wr[4];
    if (lane == 0) wr[(threadIdx.x)>>5] = term;
    __syncthreads();
    if (threadIdx.x == 0) {
        double s = (double)wr[0] + wr[1] + wr[2] + wr[3];
        atomicAdd(&g_acc[0], s);
    }
}

// ---------------- loss_pseudo: triu tiles of S = xn @ xn^T --------------------
__global__ __launch_bounds__(256)
void k_pseudo(const float* __restrict__ xall) {
    // decode triangular tile index -> (bi, bj), bj >= bi
    int t = blockIdx.x;
    float ff = (float)NB + 0.5f;
    int bi = (int)(ff - sqrtf(ff*ff - 2.0f*t));
    if (bi < 0) bi = 0; if (bi >= NB) bi = NB-1;
    while (bi > 0 && tri_off(bi) > t) bi--;
    while (tri_off(bi+1) <= t) bi++;
    int bj = bi + (t - tri_off(bi));

    __shared__ float As[32][128];
    __shared__ float Bs[32][128];
    int tid = threadIdx.x;
    int tx = tid & 15, ty = tid >> 4;
    int rA = bi * 128, rB = bj * 128;

    float acc[8][8];
#pragma unroll
    for (int i = 0; i < 8; i++)
#pragma unroll
        for (int j = 0; j < 8; j++) acc[i][j] = 0.f;

    for (int kc = 0; kc < DALL; kc += 32) {
#pragma unroll
        for (int p = 0; p < 4; p++) {
            int idx = p*256 + tid;
            int row = idx & 127;
            int k0  = (idx >> 7) * 4;
            int ga = rA + row, gb = rB + row;
            float4 va = make_float4(0.f,0.f,0.f,0.f);
            float4 vb = make_float4(0.f,0.f,0.f,0.f);
            if (ga < NN) va = *(const float4*)(xall + (size_t)ga*DALL + kc + k0);
            if (gb < NN) vb = *(const float4*)(xall + (size_t)gb*DALL + kc + k0);
            As[k0+0][row] = va.x; As[k0+1][row] = va.y;
            As[k0+2][row] = va.z; As[k0+3][row] = va.w;
            Bs[k0+0][row] = vb.x; Bs[k0+1][row] = vb.y;
            Bs[k0+2][row] = vb.z; Bs[k0+3][row] = vb.w;
        }
        __syncthreads();
#pragma unroll
        for (int k = 0; k < 32; k++) {
            float4 a0 = *(float4*)&As[k][ty*4];
            float4 a1 = *(float4*)&As[k][64 + ty*4];
            float4 c0 = *(float4*)&Bs[k][tx*4];
            float4 c1 = *(float4*)&Bs[k][64 + tx*4];
            float a[8] = {a0.x,a0.y,a0.z,a0.w,a1.x,a1.y,a1.z,a1.w};
            float c[8] = {c0.x,c0.y,c0.z,c0.w,c1.x,c1.y,c1.z,c1.w};
#pragma unroll
            for (int i = 0; i < 8; i++)
#pragma unroll
                for (int j = 0; j < 8; j++) acc[i][j] = fmaf(a[i], c[j], acc[i][j]);
        }
        __syncthreads();
    }

    // fused epilogue: mask + weighted softplus, reduced locally
    float lsum = 0.f;
#pragma unroll
    for (int i = 0; i < 8; i++) {
        int r  = (i < 4) ? (ty*4 + i) : (64 + ty*4 + (i-4));
        int gi = rA + r;
#pragma unroll
        for (int j = 0; j < 8; j++) {
            int c  = (j < 4) ? (tx*4 + j) : (64 + tx*4 + (j-4));
            int gj = rB + c;
            float s = 0.5f * acc[i][j];
            if (gj > gi && gj < NN && gi < NN && s > 0.95f) {
                float u = (s - 0.1f) * (1.0f/0.9f);
                lsum += (u*u) * log1pf(expf(g_negs[gi] - s));
            }
        }
    }
    float v = lsum;
#pragma unroll
    for (int o = 16; o; o >>= 1) v += __shfl_xor_sync(0xffffffffu, v, o);
    __shared__ double wred[8];
    if ((tid & 31) == 0) wred[tid>>5] = (double)v;
    __syncthreads();
    if (tid == 0) {
        double s = 0;
#pragma unroll
        for (int q = 0; q < 8; q++) s += wred[q];
        if (s != 0.0) atomicAdd(&g_acc[1], s);
    }
}

// ---------------- finalize ------------------------------------------------------
__global__ void k_final(float* out, int loss_idx) {
    double lc   = -g_acc[2] / (double)PP;
    double loss = g_acc[0] + g_acc[1] + 1.0 * lc;   // LAMBDA1 = 1
    out[loss_idx] = (float)loss;
}

// ---------------- launch ---------------------------------------------------------
extern "C" void kernel_launch(void* const* d_in, const int* in_sizes, int n_in,
                              void* d_out, int out_size) {
    const float* x0  = (const float*)d_in[0];
    const float* x1  = (const float*)d_in[1];
    const int*   a0s = (const int*)d_in[2];
    const int*   a0d = (const int*)d_in[3];
    const float* a0v = (const float*)d_in[4];
    const int*   a1s = (const int*)d_in[5];
    const int*   a1d = (const int*)d_in[6];
    const float* a1v = (const float*)d_in[7];
    const int*   ts  = (const int*)d_in[8];
    const int*   ngi = (const int*)d_in[9];
    const int*   ngr = (const int*)d_in[10];
    const int*   na  = (const int*)d_in[11];
    const int*   nb  = (const int*)d_in[12];
    const int*   nl  = (const int*)d_in[13];
    const float* W0  = (const float*)d_in[14];
    const float* b0  = (const float*)d_in[15];
    const float* W1  = (const float*)d_in[16];
    const float* b1  = (const float*)d_in[17];
    float* out = (float*)d_out;

    k_zero <<<(2*(NN+1)+255)/256, 256>>>();
    k_count<<<(2*EE+255)/256, 256>>>(a0d, a1d);
    k_scan <<<1, 512>>>();
    k_fill <<<(2*EE+255)/256, 256>>>(a0s, a0d, a0v, a1s, a1d, a1v);
    k_sup  <<<dim3(NB,1,2), 256>>>(x0, W0, b0, x1, W1, b1);
    k_agg  <<<dim3(NN,2), 128>>>(out);
    k_negs <<<NN/4, 128>>>(out, ngr);
    k_lc   <<<PP/4, 128>>>(out, na, nb, nl);
    k_real <<<MM/4, 128>>>(out, ts, ngi);
    k_pseudo<<<NTILES, 256>>>(out);
    k_final<<<1, 1>>>(out, out_size - 1);
}

// round 3
// speedup vs baseline: 2.0992x; 2.0992x over previous
#include <cuda_runtime.h>
#include <cuda_bf16.h>
#include <cstdint>
#include <math.h>

#define NN   10000
#define EE   320000
#define DIN  256
#define HIDN 128
#define DALL 256
#define MM   100000
#define PP   15000
#define NB   79                    // ceil(NN/128)
#define NTILES ((NB*(NB+1))/2)     // 3160 upper-tri tiles
#define KCAT 512                   // bf16 split: (hi,lo) interleaved, K = 2*256

// ---------------- static device scratch (no allocations allowed) ------------
__device__ float  g_sup[2][NN*HIDN];
__device__ int    g_off[2][NN+1];
__device__ int    g_cur[2][NN];
__device__ int    g_ssrc[2][EE];
__device__ float  g_sval[2][EE];
__device__ float  g_negs[NN];
__device__ double g_acc[3];        // [0]=loss_real  [1]=loss_pseudo  [2]=lc_sum
__device__ __align__(16) __nv_bfloat16 g_xcat[NN*KCAT];   // 10.24 MB, L2-resident

// ---------------- helpers ----------------------------------------------------
__device__ __forceinline__ int tri_off(int b) { return b*NB - (b*(b-1))/2; }

// ---------------- zero -------------------------------------------------------
__global__ void k_zero() {
    int i = blockIdx.x*blockDim.x + threadIdx.x;
    if (i < 2*(NN+1)) ((int*)g_off)[i] = 0;
    if (i < 3) g_acc[i] = 0.0;
}

// ---------------- CSR build: count ------------------------------------------
__global__ void k_count(const int* __restrict__ d0, const int* __restrict__ d1) {
    int i = blockIdx.x*blockDim.x + threadIdx.x;
    if (i < EE)            atomicAdd(&g_off[0][d0[i]+1], 1);
    else if (i < 2*EE)     atomicAdd(&g_off[1][d1[i-EE]+1], 1);
}

// ---------------- CSR build: scan (1 block, 512 threads) ---------------------
__global__ void k_scan() {
    __shared__ int part[512];
    int tid = threadIdx.x;
    const int TOT = NN+1;
    const int CH  = (TOT + 511)/512;   // 20
    for (int g = 0; g < 2; g++) {
        int s = tid*CH, e = min(s+CH, TOT);
        int sum = 0;
        for (int i = s; i < e; i++) sum += g_off[g][i];
        part[tid] = sum;
        __syncthreads();
        if (tid == 0) {
            int run = 0;
            for (int i = 0; i < 512; i++) { int v = part[i]; part[i] = run; run += v; }
        }
        __syncthreads();
        int run = part[tid];
        for (int i = s; i < e; i++) {
            run += g_off[g][i];
            g_off[g][i] = run;
            if (i < NN) g_cur[g][i] = run;
        }
        __syncthreads();
    }
}

// ---------------- CSR build: fill ---------------------------------------------
__global__ void k_fill(const int* __restrict__ s0, const int* __restrict__ d0,
                       const float* __restrict__ v0,
                       const int* __restrict__ s1, const int* __restrict__ d1,
                       const float* __restrict__ v1) {
    int i = blockIdx.x*blockDim.x + threadIdx.x;
    if (i < EE) {
        int p = atomicAdd(&g_cur[0][d0[i]], 1);
        g_ssrc[0][p] = s0[i]; g_sval[0][p] = v0[i];
    } else if (i < 2*EE) {
        int j = i - EE;
        int p = atomicAdd(&g_cur[1][d1[j]], 1);
        g_ssrc[1][p] = s1[j]; g_sval[1][p] = v1[j];
    }
}

// ---------------- sup = x @ W + b   (tiled 128x128, 8x8 microtile) -----------
__global__ __launch_bounds__(256)
void k_sup(const float* __restrict__ x0, const float* __restrict__ W0, const float* __restrict__ b0,
           const float* __restrict__ x1, const float* __restrict__ W1, const float* __restrict__ b1) {
    int g = blockIdx.z;
    const float* x = g ? x1 : x0;
    const float* W = g ? W1 : W0;
    const float* b = g ? b1 : b0;
    float* sup = g_sup[g];

    __shared__ float As[32][128];
    __shared__ float Bs[32][128];
    int tid = threadIdx.x;
    int tx = tid & 15, ty = tid >> 4;
    int rb = blockIdx.x * 128;

    float acc[8][8];
#pragma unroll
    for (int i = 0; i < 8; i++)
#pragma unroll
        for (int j = 0; j < 8; j++) acc[i][j] = 0.f;

    for (int kc = 0; kc < DIN; kc += 32) {
#pragma unroll
        for (int p = 0; p < 4; p++) {               // A transpose load
            int idx = p*256 + tid;
            int row = idx & 127;
            int k0  = (idx >> 7) * 4;
            int gr  = rb + row;
            float4 v = make_float4(0.f,0.f,0.f,0.f);
            if (gr < NN) v = *(const float4*)(x + (size_t)gr*DIN + kc + k0);
            As[k0+0][row] = v.x; As[k0+1][row] = v.y;
            As[k0+2][row] = v.z; As[k0+3][row] = v.w;
        }
#pragma unroll
        for (int p = 0; p < 4; p++) {               // W direct load
            int idx = p*256 + tid;
            int kk  = idx >> 5;
            int c4  = (idx & 31) * 4;
            float4 v = *(const float4*)(W + (size_t)(kc+kk)*HIDN + c4);
            *(float4*)&Bs[kk][c4] = v;
        }
        __syncthreads();
#pragma unroll
        for (int k = 0; k < 32; k++) {
            float4 a0 = *(float4*)&As[k][ty*4];
            float4 a1 = *(float4*)&As[k][64 + ty*4];
            float4 c0 = *(float4*)&Bs[k][tx*4];
            float4 c1 = *(float4*)&Bs[k][64 + tx*4];
            float a[8] = {a0.x,a0.y,a0.z,a0.w,a1.x,a1.y,a1.z,a1.w};
            float c[8] = {c0.x,c0.y,c0.z,c0.w,c1.x,c1.y,c1.z,c1.w};
#pragma unroll
            for (int i = 0; i < 8; i++)
#pragma unroll
                for (int j = 0; j < 8; j++) acc[i][j] = fmaf(a[i], c[j], acc[i][j]);
        }
        __syncthreads();
    }
    float4 bv0 = *(const float4*)(b + tx*4);
    float4 bv1 = *(const float4*)(b + 64 + tx*4);
    float bb[8] = {bv0.x,bv0.y,bv0.z,bv0.w,bv1.x,bv1.y,bv1.z,bv1.w};
#pragma unroll
    for (int i = 0; i < 8; i++) {
        int r  = (i < 4) ? (ty*4 + i) : (64 + ty*4 + (i-4));
        int gr = rb + r;
        if (gr < NN) {
            float4 o0 = make_float4(acc[i][0]+bb[0], acc[i][1]+bb[1],
                                    acc[i][2]+bb[2], acc[i][3]+bb[3]);
            float4 o1 = make_float4(acc[i][4]+bb[4], acc[i][5]+bb[5],
                                    acc[i][6]+bb[6], acc[i][7]+bb[7]);
            *(float4*)(sup + (size_t)gr*HIDN + tx*4)      = o0;
            *(float4*)(sup + (size_t)gr*HIDN + 64 + tx*4) = o1;
        }
    }
}

// ---------------- aggregate + l2norm -> x_all (d_out) ------------------------
__global__ __launch_bounds__(128)
void k_agg(float* __restrict__ out) {
    int n   = blockIdx.x;
    int g   = blockIdx.y;
    int tid = threadIdx.x;              // dim 0..127
    const float* sup = g_sup[g];
    __shared__ int   ss[128];
    __shared__ float sv[128];
    float acc = 0.f;
    int s0 = g_off[g][n], s1 = g_off[g][n+1];
    for (int base = s0; base < s1; base += 128) {
        int cnt = min(128, s1 - base);
        __syncthreads();
        if (tid < cnt) { ss[tid] = g_ssrc[g][base+tid]; sv[tid] = g_sval[g][base+tid]; }
        __syncthreads();
#pragma unroll 4
        for (int q = 0; q < cnt; q++)
            acc = fmaf(sup[(size_t)ss[q]*HIDN + tid], sv[q], acc);
    }
    float sq = acc*acc;
#pragma unroll
    for (int o = 16; o; o >>= 1) sq += __shfl_xor_sync(0xffffffffu, sq, o);
    __shared__ float wsum[4];
    if ((tid & 31) == 0) wsum[tid>>5] = sq;
    __syncthreads();
    float tot = wsum[0] + wsum[1] + wsum[2] + wsum[3];
    out[(size_t)n*DALL + g*HIDN + tid] = acc / sqrtf(tot);
}

// ---------------- split xn into bf16 (hi,lo) pairs -> g_xcat ------------------
// xn = x_all / sqrt(2); xcat[n][2k]=bf16(xn_k), xcat[n][2k+1]=bf16(xn_k - hi)
__global__ __launch_bounds__(256)
void k_split(const float* __restrict__ xall) {
    int i = blockIdx.x*blockDim.x + threadIdx.x;   // over NN*64 float4 groups
    if (i >= NN*64) return;
    int n = i >> 6, q = i & 63;
    float4 v = *(const float4*)(xall + (size_t)n*DALL + q*4);
    const float s = 0.70710678118654752440f;
    float xs[4] = {v.x*s, v.y*s, v.z*s, v.w*s};
    __nv_bfloat16 o[8];
#pragma unroll
    for (int j = 0; j < 4; j++) {
        __nv_bfloat16 hi = __float2bfloat16_rn(xs[j]);
        __nv_bfloat16 lo = __float2bfloat16_rn(xs[j] - __bfloat162float(hi));
        o[2*j] = hi; o[2*j+1] = lo;
    }
    *(uint4*)(g_xcat + (size_t)n*KCAT + q*8) = *(uint4*)o;
}

// ---------------- neg_s[i] = cos(x_all[i], x_all[neg_row[i]]) ----------------
__global__ __launch_bounds__(128)
void k_negs(const float* __restrict__ xall, const int* __restrict__ negrow) {
    int w    = (blockIdx.x*blockDim.x + threadIdx.x) >> 5;
    int lane = threadIdx.x & 31;
    if (w >= NN) return;
    int j = negrow[w];
    const float4* a = (const float4*)(xall + (size_t)w*DALL);
    const float4* b = (const float4*)(xall + (size_t)j*DALL);
    float s = 0.f;
#pragma unroll
    for (int q = lane; q < 64; q += 32) {
        float4 av = a[q], bv = b[q];
        s += av.x*bv.x + av.y*bv.y + av.z*bv.z + av.w*bv.w;
    }
#pragma unroll
    for (int o = 16; o; o >>= 1) s += __shfl_xor_sync(0xffffffffu, s, o);
    if (lane == 0) g_negs[w] = 0.5f*s;   // norms are exactly sqrt(2)
}

// ---------------- lc (P pairs) ------------------------------------------------
__global__ __launch_bounds__(128)
void k_lc(const float* __restrict__ xall, const int* __restrict__ na,
          const int* __restrict__ nbv, const int* __restrict__ nl) {
    int w    = (blockIdx.x*blockDim.x + threadIdx.x) >> 5;
    int lane = threadIdx.x & 31;
    float term = 0.f;
    if (w < PP) {
        int ia = na[w], ib = nbv[w];
        const float4* a = (const float4*)(xall + (size_t)ia*DALL);
        const float4* b = (const float4*)(xall + (size_t)ib*DALL);
        float s = 0.f;
#pragma unroll
        for (int q = lane; q < 64; q += 32) {
            float4 av = a[q], bv = b[q];
            s += av.x*bv.x + av.y*bv.y + av.z*bv.z + av.w*bv.w;
        }
#pragma unroll
        for (int o = 16; o; o >>= 1) s += __shfl_xor_sync(0xffffffffu, s, o);
        if (lane == 0) {
            float sim = 0.5f*s;
            float z   = sim * 2.0f;                       // sim / TAU0, TAU0=0.5
            float ls  = (z >= 0.f) ? -log1pf(expf(-z)) : (z - log1pf(expf(z)));
            int   L   = nl[w];
            term = ldexpf(1.0f, -(L+1)) * ls;             // 0.5^(L+1), exact
        }
    }
    __shared__ float wr[4];
    if (lane == 0) wr[(threadIdx.x)>>5] = term;
    __syncthreads();
    if (threadIdx.x == 0) {
        double s = (double)wr[0] + wr[1] + wr[2] + wr[3];
        atomicAdd(&g_acc[2], s);
    }
}

// ---------------- loss_real (M pairs) -----------------------------------------
__global__ __launch_bounds__(128)
void k_real(const float* __restrict__ xall, const int* __restrict__ ts,
            const int* __restrict__ negidx) {
    int w    = (blockIdx.x*blockDim.x + threadIdx.x) >> 5;
    int lane = threadIdx.x & 31;
    float term = 0.f;
    if (w < MM) {
        int t0 = ts[2*w], t1 = ts[2*w+1], tn = negidx[w];
        const float4* rs = (const float4*)(xall + (size_t)t0*DALL);
        const float4* re = (const float4*)(xall + (size_t)t1*DALL);
        const float4* ng = (const float4*)(xall + (size_t)tn*DALL);
        float ps = 0.f, ns = 0.f;
#pragma unroll
        for (int q = lane; q < 64; q += 32) {
            float4 r = rs[q], e = re[q], n = ng[q];
            ps += r.x*e.x + r.y*e.y + r.z*e.z + r.w*e.w;
            ns += r.x*n.x + r.y*n.y + r.z*n.z + r.w*n.w;
        }
#pragma unroll
        for (int o = 16; o; o >>= 1) {
            ps += __shfl_xor_sync(0xffffffffu, ps, o);
            ns += __shfl_xor_sync(0xffffffffu, ns, o);
        }
        if (lane == 0) {
            float pos = 0.5f*ps, neg = 0.5f*ns;
            float u = (pos - 0.1f) * (1.0f/0.9f);
            term = (u*u) * log1pf(expf(neg - pos));
        }
    }
    __shared__ float wr[4];
    if (lane == 0) wr[(threadIdx.x)>>5] = term;
    __syncthreads();
    if (threadIdx.x == 0) {
        double s = (double)wr[0] + wr[1] + wr[2] + wr[3];
        atomicAdd(&g_acc[0], s);
    }
}

// ---------------- loss_pseudo: bf16 tensor-core GEMM over triu tiles ----------
// S-tile = Xcat[biBlock] @ Xcat[bjBlock]^T, K = 512 bf16 (hi/lo interleaved),
// fp32 accumulate; fused masked-softplus epilogue.
__global__ __launch_bounds__(256, 2)
void k_pseudo() {
    // decode triangular tile index -> (bi, bj), bj >= bi
    int t = blockIdx.x;
    float ff = (float)NB + 0.5f;
    int bi = (int)(ff - sqrtf(ff*ff - 2.0f*t));
    if (bi < 0) bi = 0; if (bi >= NB) bi = NB-1;
    while (bi > 0 && tri_off(bi) > t) bi--;
    while (tri_off(bi+1) <= t) bi++;
    int bj = bi + (t - tri_off(bi));
    int rA = bi * 128, rB = bj * 128;

    // swizzled smem: row stride 128B; 16B chunk c of row r stored at (c*16) ^ ((r&7)*16)
    __shared__ __align__(16) char As[128*128];
    __shared__ __align__(16) char Bs[128*128];

    int tid  = threadIdx.x;
    int lane = tid & 31;
    int wid  = tid >> 5;
    int wm   = (wid >> 2) * 64;     // warp row offset (2 warp-rows)
    int wn   = (wid & 3)  * 32;     // warp col offset (4 warp-cols)

    float acc[4][4][4];
#pragma unroll
    for (int a = 0; a < 4; a++)
#pragma unroll
        for (int b = 0; b < 4; b++)
#pragma unroll
            for (int c = 0; c < 4; c++) acc[a][b][c] = 0.f;

    const char* xbytes = (const char*)g_xcat;

    for (int kc = 0; kc < KCAT; kc += 64) {      // 8 chunks of 64 bf16 (128B/row)
        // load A and B tiles: 128 rows x 128B each; 256 threads x 4 chunks x 2 tiles
#pragma unroll
        for (int p = 0; p < 4; p++) {
            int idx = p*256 + tid;
            int row = idx >> 3;
            int cb  = (idx & 7) * 16;            // byte col within chunk row
            int sw  = row*128 + (cb ^ ((row & 7) * 16));
            int ga = rA + row, gb = rB + row;
            uint4 va = make_uint4(0u,0u,0u,0u), vb = make_uint4(0u,0u,0u,0u);
            if (ga < NN) va = *(const uint4*)(xbytes + (size_t)ga*(KCAT*2) + kc*2 + cb);
            if (gb < NN) vb = *(const uint4*)(xbytes + (size_t)gb*(KCAT*2) + kc*2 + cb);
            *(uint4*)(As + sw) = va;
            *(uint4*)(Bs + sw) = vb;
        }
        __syncthreads();

#pragma unroll
        for (int ks = 0; ks < 4; ks++) {         // 4 x k16 steps
            uint32_t afr[4][4];
            uint32_t bfr[2][4];
            int cbk = ks*32 + (lane >> 4)*16;    // byte col for this lane's matrix
#pragma unroll
            for (int mb = 0; mb < 4; mb++) {
                int row = wm + mb*16 + (lane & 15);
                uint32_t sa = (uint32_t)__cvta_generic_to_shared(
                                  As + row*128 + (cbk ^ ((row & 7) * 16)));
                asm volatile("ldmatrix.sync.aligned.m8n8.x4.shared.b16 {%0,%1,%2,%3}, [%4];"
                    : "=r"(afr[mb][0]), "=r"(afr[mb][1]), "=r"(afr[mb][2]), "=r"(afr[mb][3])
                    : "r"(sa));
            }
#pragma unroll
            for (int nb2 = 0; nb2 < 2; nb2++) {
                int row = wn + nb2*16 + (lane & 15);
                uint32_t sb = (uint32_t)__cvta_generic_to_shared(
                                  Bs + row*128 + (cbk ^ ((row & 7) * 16)));
                asm volatile("ldmatrix.sync.aligned.m8n8.x4.shared.b16 {%0,%1,%2,%3}, [%4];"
                    : "=r"(bfr[nb2][0]), "=r"(bfr[nb2][1]), "=r"(bfr[nb2][2]), "=r"(bfr[nb2][3])
                    : "r"(sb));
            }
#pragma unroll
            for (int mb = 0; mb < 4; mb++)
#pragma unroll
                for (int nb = 0; nb < 4; nb++) {
                    int h = nb >> 1, o = nb & 1;
                    asm volatile(
                        "mma.sync.aligned.m16n8k16.row.col.f32.bf16.bf16.f32 "
                        "{%0,%1,%2,%3}, {%4,%5,%6,%7}, {%8,%9}, {%0,%1,%2,%3};"
                        : "+f"(acc[mb][nb][0]), "+f"(acc[mb][nb][1]),
                          "+f"(acc[mb][nb][2]), "+f"(acc[mb][nb][3])
                        : "r"(afr[mb][0]), "r"(afr[mb][1]), "r"(afr[mb][2]), "r"(afr[mb][3]),
                          "r"(bfr[h][o]),  "r"(bfr[h][o+2]));
                }
        }
        __syncthreads();
    }

    // fused epilogue: s = acc directly (xn dot xn); mask + weighted softplus
    float lsum = 0.f;
#pragma unroll
    for (int mb = 0; mb < 4; mb++) {
        int r0 = rA + wm + mb*16 + (lane >> 2);
#pragma unroll
        for (int nb = 0; nb < 4; nb++) {
            int c0 = rB + wn + nb*8 + (lane & 3)*2;
#pragma unroll
            for (int e = 0; e < 4; e++) {
                int gi = r0 + (e >= 2 ? 8 : 0);
                int gj = c0 + (e & 1);
                float s = acc[mb][nb][e];
                if (gj > gi && gj < NN && gi < NN && s > 0.95f) {
                    float u = (s - 0.1f) * (1.0f/0.9f);
                    lsum += (u*u) * log1pf(expf(g_negs[gi] - s));
                }
            }
        }
    }
    float v = lsum;
#pragma unroll
    for (int o = 16; o; o >>= 1) v += __shfl_xor_sync(0xffffffffu, v, o);
    __shared__ double wred[8];
    if ((lane) == 0) wred[wid] = (double)v;
    __syncthreads();
    if (tid == 0) {
        double s = 0;
#pragma unroll
        for (int q = 0; q < 8; q++) s += wred[q];
        if (s != 0.0) atomicAdd(&g_acc[1], s);
    }
}

// ---------------- finalize ------------------------------------------------------
__global__ void k_final(float* out, int loss_idx) {
    double lc   = -g_acc[2] / (double)PP;
    double loss = g_acc[0] + g_acc[1] + 1.0 * lc;   // LAMBDA1 = 1
    out[loss_idx] = (float)loss;
}

// ---------------- launch ---------------------------------------------------------
extern "C" void kernel_launch(void* const* d_in, const int* in_sizes, int n_in,
                              void* d_out, int out_size) {
    const float* x0  = (const float*)d_in[0];
    const float* x1  = (const float*)d_in[1];
    const int*   a0s = (const int*)d_in[2];
    const int*   a0d = (const int*)d_in[3];
    const float* a0v = (const float*)d_in[4];
    const int*   a1s = (const int*)d_in[5];
    const int*   a1d = (const int*)d_in[6];
    const float* a1v = (const float*)d_in[7];
    const int*   ts  = (const int*)d_in[8];
    const int*   ngi = (const int*)d_in[9];
    const int*   ngr = (const int*)d_in[10];
    const int*   na  = (const int*)d_in[11];
    const int*   nb  = (const int*)d_in[12];
    const int*   nl  = (const int*)d_in[13];
    const float* W0  = (const float*)d_in[14];
    const float* b0  = (const float*)d_in[15];
    const float* W1  = (const float*)d_in[16];
    const float* b1  = (const float*)d_in[17];
    float* out = (float*)d_out;

    k_zero <<<(2*(NN+1)+255)/256, 256>>>();
    k_count<<<(2*EE+255)/256, 256>>>(a0d, a1d);
    k_scan <<<1, 512>>>();
    k_fill <<<(2*EE+255)/256, 256>>>(a0s, a0d, a0v, a1s, a1d, a1v);
    k_sup  <<<dim3(NB,1,2), 256>>>(x0, W0, b0, x1, W1, b1);
    k_agg  <<<dim3(NN,2), 128>>>(out);
    k_split<<<(NN*64+255)/256, 256>>>(out);
    k_negs <<<NN/4, 128>>>(out, ngr);
    k_lc   <<<PP/4, 128>>>(out, na, nb, nl);
    k_real <<<MM/4, 128>>>(out, ts, ngi);
    k_pseudo<<<NTILES, 256>>>();
    k_final<<<1, 1>>>(out, out_size - 1);
}

// round 4
// speedup vs baseline: 2.1186x; 1.0092x over previous
#include <cuda_runtime.h>
#include <cuda_bf16.h>
#include <cstdint>
#include <math.h>

#define NN   10000
#define EE   320000
#define DIN  256
#define HIDN 128
#define DALL 256
#define MM   100000
#define PP   15000
#define NB   79                    // ceil(NN/128)
#define NTILES ((NB*(NB+1))/2)     // 3160 upper-tri tiles
#define KCAT 512                   // bf16 split: (hi,lo) interleaved, K = 2*256
#define NRB  (MM/8)                // 12500 real blocks (8 pairs/block)
#define NLB  (PP/8)                // 1875 lc blocks
#define TOTALB (NTILES + NRB + NLB)

// ---------------- static device scratch (no allocations allowed) ------------
__device__ float  g_sup[2][NN*HIDN];
__device__ int    g_off[2][NN+1];
__device__ int    g_cur[2][NN];
__device__ int    g_ssrc[2][EE];
__device__ float  g_sval[2][EE];
__device__ float  g_negs[NN];
__device__ double g_acc[3];        // [0]=loss_real  [1]=loss_pseudo  [2]=lc_sum
__device__ __align__(16) __nv_bfloat16 g_xcat[NN*KCAT];   // 10.24 MB, L2-resident

// ---------------- helpers ----------------------------------------------------
__device__ __forceinline__ int tri_off(int b) { return b*NB - (b*(b-1))/2; }

// ---------------- zero -------------------------------------------------------
__global__ void k_zero() {
    int i = blockIdx.x*blockDim.x + threadIdx.x;
    if (i < 2*(NN+1)) ((int*)g_off)[i] = 0;
    if (i < 3) g_acc[i] = 0.0;
}

// ---------------- CSR build: count ------------------------------------------
__global__ void k_count(const int* __restrict__ d0, const int* __restrict__ d1) {
    int i = blockIdx.x*blockDim.x + threadIdx.x;
    if (i < EE)            atomicAdd(&g_off[0][d0[i]+1], 1);
    else if (i < 2*EE)     atomicAdd(&g_off[1][d1[i-EE]+1], 1);
}

// ---------------- CSR build: scan (1 block, 512 threads) ---------------------
__global__ void k_scan() {
    __shared__ int part[512];
    int tid = threadIdx.x;
    const int TOT = NN+1;
    const int CH  = (TOT + 511)/512;   // 20
    for (int g = 0; g < 2; g++) {
        int s = tid*CH, e = min(s+CH, TOT);
        int sum = 0;
        for (int i = s; i < e; i++) sum += g_off[g][i];
        part[tid] = sum;
        __syncthreads();
        if (tid == 0) {
            int run = 0;
            for (int i = 0; i < 512; i++) { int v = part[i]; part[i] = run; run += v; }
        }
        __syncthreads();
        int run = part[tid];
        for (int i = s; i < e; i++) {
            run += g_off[g][i];
            g_off[g][i] = run;
            if (i < NN) g_cur[g][i] = run;
        }
        __syncthreads();
    }
}

// ---------------- CSR build: fill ---------------------------------------------
__global__ void k_fill(const int* __restrict__ s0, const int* __restrict__ d0,
                       const float* __restrict__ v0,
                       const int* __restrict__ s1, const int* __restrict__ d1,
                       const float* __restrict__ v1) {
    int i = blockIdx.x*blockDim.x + threadIdx.x;
    if (i < EE) {
        int p = atomicAdd(&g_cur[0][d0[i]], 1);
        g_ssrc[0][p] = s0[i]; g_sval[0][p] = v0[i];
    } else if (i < 2*EE) {
        int j = i - EE;
        int p = atomicAdd(&g_cur[1][d1[j]], 1);
        g_ssrc[1][p] = s1[j]; g_sval[1][p] = v1[j];
    }
}

// ---------------- sup = x @ W + b   (tiled 128x128, 8x8 microtile) -----------
__global__ __launch_bounds__(256)
void k_sup(const float* __restrict__ x0, const float* __restrict__ W0, const float* __restrict__ b0,
           const float* __restrict__ x1, const float* __restrict__ W1, const float* __restrict__ b1) {
    int g = blockIdx.z;
    const float* x = g ? x1 : x0;
    const float* W = g ? W1 : W0;
    const float* b = g ? b1 : b0;
    float* sup = g_sup[g];

    __shared__ float As[32][128];
    __shared__ float Bs[32][128];
    int tid = threadIdx.x;
    int tx = tid & 15, ty = tid >> 4;
    int rb = blockIdx.x * 128;

    float acc[8][8];
#pragma unroll
    for (int i = 0; i < 8; i++)
#pragma unroll
        for (int j = 0; j < 8; j++) acc[i][j] = 0.f;

    for (int kc = 0; kc < DIN; kc += 32) {
#pragma unroll
        for (int p = 0; p < 4; p++) {               // A transpose load
            int idx = p*256 + tid;
            int row = idx & 127;
            int k0  = (idx >> 7) * 4;
            int gr  = rb + row;
            float4 v = make_float4(0.f,0.f,0.f,0.f);
            if (gr < NN) v = *(const float4*)(x + (size_t)gr*DIN + kc + k0);
            As[k0+0][row] = v.x; As[k0+1][row] = v.y;
            As[k0+2][row] = v.z; As[k0+3][row] = v.w;
        }
#pragma unroll
        for (int p = 0; p < 4; p++) {               // W direct load
            int idx = p*256 + tid;
            int kk  = idx >> 5;
            int c4  = (idx & 31) * 4;
            float4 v = *(const float4*)(W + (size_t)(kc+kk)*HIDN + c4);
            *(float4*)&Bs[kk][c4] = v;
        }
        __syncthreads();
#pragma unroll
        for (int k = 0; k < 32; k++) {
            float4 a0 = *(float4*)&As[k][ty*4];
            float4 a1 = *(float4*)&As[k][64 + ty*4];
            float4 c0 = *(float4*)&Bs[k][tx*4];
            float4 c1 = *(float4*)&Bs[k][64 + tx*4];
            float a[8] = {a0.x,a0.y,a0.z,a0.w,a1.x,a1.y,a1.z,a1.w};
            float c[8] = {c0.x,c0.y,c0.z,c0.w,c1.x,c1.y,c1.z,c1.w};
#pragma unroll
            for (int i = 0; i < 8; i++)
#pragma unroll
                for (int j = 0; j < 8; j++) acc[i][j] = fmaf(a[i], c[j], acc[i][j]);
        }
        __syncthreads();
    }
    float4 bv0 = *(const float4*)(b + tx*4);
    float4 bv1 = *(const float4*)(b + 64 + tx*4);
    float bb[8] = {bv0.x,bv0.y,bv0.z,bv0.w,bv1.x,bv1.y,bv1.z,bv1.w};
#pragma unroll
    for (int i = 0; i < 8; i++) {
        int r  = (i < 4) ? (ty*4 + i) : (64 + ty*4 + (i-4));
        int gr = rb + r;
        if (gr < NN) {
            float4 o0 = make_float4(acc[i][0]+bb[0], acc[i][1]+bb[1],
                                    acc[i][2]+bb[2], acc[i][3]+bb[3]);
            float4 o1 = make_float4(acc[i][4]+bb[4], acc[i][5]+bb[5],
                                    acc[i][6]+bb[6], acc[i][7]+bb[7]);
            *(float4*)(sup + (size_t)gr*HIDN + tx*4)      = o0;
            *(float4*)(sup + (size_t)gr*HIDN + 64 + tx*4) = o1;
        }
    }
}

// ---------------- aggregate + l2norm -> x_all (d_out) + fused bf16 split -----
__global__ __launch_bounds__(128)
void k_agg(float* __restrict__ out) {
    int n   = blockIdx.x;
    int g   = blockIdx.y;
    int tid = threadIdx.x;              // dim 0..127
    const float* sup = g_sup[g];
    __shared__ int   ss[128];
    __shared__ float sv[128];
    float acc = 0.f;
    int s0 = g_off[g][n], s1 = g_off[g][n+1];
    for (int base = s0; base < s1; base += 128) {
        int cnt = min(128, s1 - base);
        __syncthreads();
        if (tid < cnt) { ss[tid] = g_ssrc[g][base+tid]; sv[tid] = g_sval[g][base+tid]; }
        __syncthreads();
#pragma unroll 4
        for (int q = 0; q < cnt; q++)
            acc = fmaf(sup[(size_t)ss[q]*HIDN + tid], sv[q], acc);
    }
    float sq = acc*acc;
#pragma unroll
    for (int o = 16; o; o >>= 1) sq += __shfl_xor_sync(0xffffffffu, sq, o);
    __shared__ float wsum[4];
    if ((tid & 31) == 0) wsum[tid>>5] = sq;
    __syncthreads();
    float tot = wsum[0] + wsum[1] + wsum[2] + wsum[3];
    float v = acc / sqrtf(tot);
    out[(size_t)n*DALL + g*HIDN + tid] = v;

    // fused bf16 hi/lo split of xn = v / sqrt(2)
    float xs = v * 0.70710678118654752440f;
    __nv_bfloat16 hi = __float2bfloat16_rn(xs);
    __nv_bfloat16 lo = __float2bfloat16_rn(xs - __bfloat162float(hi));
    __nv_bfloat16 pk[2] = {hi, lo};
    ((uint32_t*)g_xcat)[(size_t)n*256 + g*128 + tid] = *(uint32_t*)pk;
}

// ---------------- neg_s[i] = cos(x_all[i], x_all[neg_row[i]]) ----------------
__global__ __launch_bounds__(128)
void k_negs(const float* __restrict__ xall, const int* __restrict__ negrow) {
    int w    = (blockIdx.x*blockDim.x + threadIdx.x) >> 5;
    int lane = threadIdx.x & 31;
    if (w >= NN) return;
    int j = negrow[w];
    const float4* a = (const float4*)(xall + (size_t)w*DALL);
    const float4* b = (const float4*)(xall + (size_t)j*DALL);
    float s = 0.f;
#pragma unroll
    for (int q = lane; q < 64; q += 32) {
        float4 av = a[q], bv = b[q];
        s += av.x*bv.x + av.y*bv.y + av.z*bv.z + av.w*bv.w;
    }
#pragma unroll
    for (int o = 16; o; o >>= 1) s += __shfl_xor_sync(0xffffffffu, s, o);
    if (lane == 0) g_negs[w] = 0.5f*s;   // norms are exactly sqrt(2)
}

// ================= MEGA kernel: pseudo GEMM ∥ loss_real ∥ lc ==================
// Block roles interleaved Bresenham-style so every wave mixes tensor-bound
// GEMM blocks with L2-gather loss blocks.

__device__ __forceinline__ void cpa16(uint32_t smem_dst, const void* gsrc, int valid) {
    asm volatile("cp.async.cg.shared.global [%0], [%1], 16, %2;\n"
                 :: "r"(smem_dst), "l"(gsrc), "r"(valid ? 16 : 0));
}

__global__ __launch_bounds__(256, 2)
void k_mega(const float* __restrict__ xall, const int* __restrict__ ts,
            const int* __restrict__ negidx, const int* __restrict__ na,
            const int* __restrict__ nbv, const int* __restrict__ nl) {
    // double-buffered GEMM tiles: 2 stages x (A 16KB + B 16KB) = 64KB
    __shared__ __align__(128) char As[2][16384];
    __shared__ __align__(128) char Bs[2][16384];
    __shared__ double wred[8];
    __shared__ float  wr[8];

    int b    = blockIdx.x;
    int tid  = threadIdx.x;
    int lane = tid & 31;
    int wid  = tid >> 5;

    // ----- role decode (Bresenham spread) -----
    long long beforeP = (long long)b * NTILES / TOTALB;
    long long afterP  = (long long)(b+1) * NTILES / TOTALB;

    if (afterP > beforeP) {
        // ================= PSEUDO GEMM role =================
        int t = (int)beforeP;
        float ff = (float)NB + 0.5f;
        int bi = (int)(ff - sqrtf(ff*ff - 2.0f*t));
        if (bi < 0) bi = 0; if (bi >= NB) bi = NB-1;
        while (bi > 0 && tri_off(bi) > t) bi--;
        while (tri_off(bi+1) <= t) bi++;
        int bj = bi + (t - tri_off(bi));
        int rA = bi * 128, rB = bj * 128;

        int wm = (wid >> 2) * 64;     // warp row offset
        int wn = (wid & 3)  * 32;     // warp col offset

        float acc[4][4][4];
#pragma unroll
        for (int a = 0; a < 4; a++)
#pragma unroll
            for (int bq = 0; bq < 4; bq++)
#pragma unroll
                for (int c = 0; c < 4; c++) acc[a][bq][c] = 0.f;

        const char* xbytes = (const char*)g_xcat;

        // per-thread fixed load slot: 4 (row, 16B-chunk) pairs per stage side
        int r0 = tid >> 3;                 // rows r0, r0+32, r0+64, r0+96
        int cb = (tid & 7) * 16;           // byte col within 128B chunk row

        // prefetch chunk 0 -> stage 0
        {
            uint32_t a0 = (uint32_t)__cvta_generic_to_shared(As[0]);
            uint32_t b0 = (uint32_t)__cvta_generic_to_shared(Bs[0]);
#pragma unroll
            for (int p = 0; p < 4; p++) {
                int row = r0 + p*32;
                int sw  = row*128 + (cb ^ ((row & 7) * 16));
                int ga = rA + row, gb = rB + row;
                cpa16(a0 + sw, xbytes + (size_t)min(ga, NN-1)*1024 + cb, ga < NN);
                cpa16(b0 + sw, xbytes + (size_t)min(gb, NN-1)*1024 + cb, gb < NN);
            }
            asm volatile("cp.async.commit_group;\n");
        }

        for (int c = 0; c < 8; c++) {
            if (c < 7) {   // prefetch chunk c+1 into stage (c+1)&1
                int st = (c+1) & 1;
                uint32_t a0 = (uint32_t)__cvta_generic_to_shared(As[st]);
                uint32_t b0 = (uint32_t)__cvta_generic_to_shared(Bs[st]);
#pragma unroll
                for (int p = 0; p < 4; p++) {
                    int row = r0 + p*32;
                    int sw  = row*128 + (cb ^ ((row & 7) * 16));
                    int ga = rA + row, gb = rB + row;
                    const char* srcA = xbytes + (size_t)min(ga, NN-1)*1024 + (c+1)*128 + cb;
                    const char* srcB = xbytes + (size_t)min(gb, NN-1)*1024 + (c+1)*128 + cb;
                    cpa16(a0 + sw, srcA, ga < NN);
                    cpa16(b0 + sw, srcB, gb < NN);
                }
                asm volatile("cp.async.commit_group;\n");
                asm volatile("cp.async.wait_group 1;\n");
            } else {
                asm volatile("cp.async.wait_group 0;\n");
            }
            __syncthreads();

            int st = c & 1;
            const char* Ab = As[st];
            const char* Bb = Bs[st];
#pragma unroll
            for (int ks = 0; ks < 4; ks++) {
                uint32_t afr[4][4];
                uint32_t bfr[2][4];
                int cbk = ks*32 + (lane >> 4)*16;
#pragma unroll
                for (int mb = 0; mb < 4; mb++) {
                    int row = wm + mb*16 + (lane & 15);
                    uint32_t sa = (uint32_t)__cvta_generic_to_shared(
                                      Ab + row*128 + (cbk ^ ((row & 7) * 16)));
                    asm volatile("ldmatrix.sync.aligned.m8n8.x4.shared.b16 {%0,%1,%2,%3}, [%4];"
                        : "=r"(afr[mb][0]), "=r"(afr[mb][1]), "=r"(afr[mb][2]), "=r"(afr[mb][3])
                        : "r"(sa));
                }
#pragma unroll
                for (int nb2 = 0; nb2 < 2; nb2++) {
                    int row = wn + nb2*16 + (lane & 15);
                    uint32_t sb = (uint32_t)__cvta_generic_to_shared(
                                      Bb + row*128 + (cbk ^ ((row & 7) * 16)));
                    asm volatile("ldmatrix.sync.aligned.m8n8.x4.shared.b16 {%0,%1,%2,%3}, [%4];"
                        : "=r"(bfr[nb2][0]), "=r"(bfr[nb2][1]), "=r"(bfr[nb2][2]), "=r"(bfr[nb2][3])
                        : "r"(sb));
                }
#pragma unroll
                for (int mb = 0; mb < 4; mb++)
#pragma unroll
                    for (int nb = 0; nb < 4; nb++) {
                        int h = nb >> 1, o = nb & 1;
                        asm volatile(
                            "mma.sync.aligned.m16n8k16.row.col.f32.bf16.bf16.f32 "
                            "{%0,%1,%2,%3}, {%4,%5,%6,%7}, {%8,%9}, {%0,%1,%2,%3};"
                            : "+f"(acc[mb][nb][0]), "+f"(acc[mb][nb][1]),
                              "+f"(acc[mb][nb][2]), "+f"(acc[mb][nb][3])
                            : "r"(afr[mb][0]), "r"(afr[mb][1]), "r"(afr[mb][2]), "r"(afr[mb][3]),
                              "r"(bfr[h][o]),  "r"(bfr[h][o+2]));
                    }
            }
            __syncthreads();
        }

        // fused epilogue: mask + weighted softplus
        float lsum = 0.f;
#pragma unroll
        for (int mb = 0; mb < 4; mb++) {
            int rr0 = rA + wm + mb*16 + (lane >> 2);
#pragma unroll
            for (int nb = 0; nb < 4; nb++) {
                int c0 = rB + wn + nb*8 + (lane & 3)*2;
#pragma unroll
                for (int e = 0; e < 4; e++) {
                    int gi = rr0 + (e >= 2 ? 8 : 0);
                    int gj = c0 + (e & 1);
                    float s = acc[mb][nb][e];
                    if (gj > gi && gj < NN && gi < NN && s > 0.95f) {
                        float u = (s - 0.1f) * (1.0f/0.9f);
                        lsum += (u*u) * log1pf(expf(g_negs[gi] - s));
                    }
                }
            }
        }
        float v = lsum;
#pragma unroll
        for (int o = 16; o; o >>= 1) v += __shfl_xor_sync(0xffffffffu, v, o);
        if (lane == 0) wred[wid] = (double)v;
        __syncthreads();
        if (tid == 0) {
            double s = 0;
#pragma unroll
            for (int q = 0; q < 8; q++) s += wred[q];
            if (s != 0.0) atomicAdd(&g_acc[1], s);
        }
        return;
    }

    // ----- non-pseudo: split into lc / real by second Bresenham spread -----
    long long r = b - beforeP;                      // rank among non-pseudo
    const long long NONP = (long long)NRB + NLB;
    long long beforeL = r * NLB / NONP;
    long long afterL  = (r+1) * NLB / NONP;

    if (afterL > beforeL) {
        // ================= LC role: 8 pairs, 1 per warp =================
        int pid = (int)beforeL * 8 + wid;
        float term = 0.f;
        {
            int ia = na[pid], ib = nbv[pid];
            const float4* a = (const float4*)(xall + (size_t)ia*DALL);
            const float4* bb = (const float4*)(xall + (size_t)ib*DALL);
            float s = 0.f;
#pragma unroll
            for (int q = lane; q < 64; q += 32) {
                float4 av = a[q], bv = bb[q];
                s += av.x*bv.x + av.y*bv.y + av.z*bv.z + av.w*bv.w;
            }
#pragma unroll
            for (int o = 16; o; o >>= 1) s += __shfl_xor_sync(0xffffffffu, s, o);
            if (lane == 0) {
                float sim = 0.5f*s;
                float z   = sim * 2.0f;               // sim / TAU0
                float ls  = (z >= 0.f) ? -log1pf(expf(-z)) : (z - log1pf(expf(z)));
                int   L   = nl[pid];
                term = ldexpf(1.0f, -(L+1)) * ls;     // GAMMA^(L+1) = 0.5^(L+1)
            }
        }
        if (lane == 0) wr[wid] = term;
        __syncthreads();
        if (tid == 0) {
            double s = 0;
#pragma unroll
            for (int q = 0; q < 8; q++) s += (double)wr[q];
            atomicAdd(&g_acc[2], s);
        }
    } else {
        // ================= REAL role: 8 pairs, 1 per warp =================
        int pid = (int)(r - beforeL) * 8 + wid;
        float term = 0.f;
        {
            int t0 = ts[2*pid], t1 = ts[2*pid+1], tn = negidx[pid];
            const float4* rs = (const float4*)(xall + (size_t)t0*DALL);
            const float4* re = (const float4*)(xall + (size_t)t1*DALL);
            const float4* ng = (const float4*)(xall + (size_t)tn*DALL);
            float ps = 0.f, ns = 0.f;
#pragma unroll
            for (int q = lane; q < 64; q += 32) {
                float4 rv = rs[q], e = re[q], n = ng[q];
                ps += rv.x*e.x + rv.y*e.y + rv.z*e.z + rv.w*e.w;
                ns += rv.x*n.x + rv.y*n.y + rv.z*n.z + rv.w*n.w;
            }
#pragma unroll
            for (int o = 16; o; o >>= 1) {
                ps += __shfl_xor_sync(0xffffffffu, ps, o);
                ns += __shfl_xor_sync(0xffffffffu, ns, o);
            }
            if (lane == 0) {
                float pos = 0.5f*ps, neg = 0.5f*ns;
                float u = (pos - 0.1f) * (1.0f/0.9f);
                term = (u*u) * log1pf(expf(neg - pos));
            }
        }
        if (lane == 0) wr[wid] = term;
        __syncthreads();
        if (tid == 0) {
            double s = 0;
#pragma unroll
            for (int q = 0; q < 8; q++) s += (double)wr[q];
            atomicAdd(&g_acc[0], s);
        }
    }
}

// ---------------- finalize ------------------------------------------------------
__global__ void k_final(float* out, int loss_idx) {
    double lc   = -g_acc[2] / (double)PP;
    double loss = g_acc[0] + g_acc[1] + 1.0 * lc;   // LAMBDA1 = 1
    out[loss_idx] = (float)loss;
}

// ---------------- launch ---------------------------------------------------------
extern "C" void kernel_launch(void* const* d_in, const int* in_sizes, int n_in,
                              void* d_out, int out_size) {
    const float* x0  = (const float*)d_in[0];
    const float* x1  = (const float*)d_in[1];
    const int*   a0s = (const int*)d_in[2];
    const int*   a0d = (const int*)d_in[3];
    const float* a0v = (const float*)d_in[4];
    const int*   a1s = (const int*)d_in[5];
    const int*   a1d = (const int*)d_in[6];
    const float* a1v = (const float*)d_in[7];
    const int*   ts  = (const int*)d_in[8];
    const int*   ngi = (const int*)d_in[9];
    const int*   ngr = (const int*)d_in[10];
    const int*   na  = (const int*)d_in[11];
    const int*   nb  = (const int*)d_in[12];
    const int*   nl  = (const int*)d_in[13];
    const float* W0  = (const float*)d_in[14];
    const float* b0  = (const float*)d_in[15];
    const float* W1  = (const float*)d_in[16];
    const float* b1  = (const float*)d_in[17];
    float* out = (float*)d_out;

    k_zero <<<(2*(NN+1)+255)/256, 256>>>();
    k_count<<<(2*EE+255)/256, 256>>>(a0d, a1d);
    k_scan <<<1, 512>>>();
    k_fill <<<(2*EE+255)/256, 256>>>(a0s, a0d, a0v, a1s, a1d, a1v);
    k_sup  <<<dim3(NB,1,2), 256>>>(x0, W0, b0, x1, W1, b1);
    k_agg  <<<dim3(NN,2), 128>>>(out);
    k_negs <<<NN/4, 128>>>(out, ngr);
    k_mega <<<TOTALB, 256>>>(out, ts, ngi, na, nb, nl);
    k_final<<<1, 1>>>(out, out_size - 1);
}

// round 6
// speedup vs baseline: 2.2951x; 1.0833x over previous
#include <cuda_runtime.h>
#include <cuda_bf16.h>
#include <cstdint>
#include <math.h>

#define NN   10000
#define EE   320000
#define DIN  256
#define HIDN 128
#define DALL 256
#define MM   100000
#define PP   15000
#define NB   79                    // ceil(NN/128)
#define NTILES ((NB*(NB+1))/2)     // 3160 upper-tri tiles
#define KBF  256                   // single bf16 per element, K = 256
#define NRB  (MM/8)                // 12500 real blocks (8 pairs/block)
#define NLB  (PP/8)                // 1875 lc blocks
#define TOTALB (NTILES + NRB + NLB)

// ---------------- static device scratch (no allocations allowed) ------------
__device__ float  g_sup[2][NN*HIDN];
__device__ int    g_off[2][NN+1];
__device__ int    g_cur[2][NN];
__device__ int    g_ssrc[2][EE];
__device__ float  g_sval[2][EE];
__device__ float  g_negs[NN];
__device__ double g_acc[3];        // [0]=loss_real  [1]=loss_pseudo  [2]=lc_sum
__device__ __align__(16) __nv_bfloat16 g_xcat[NN*KBF];   // 5.12 MB, L2-resident

// ---------------- helpers ----------------------------------------------------
__device__ __forceinline__ int tri_off(int b) { return b*NB - (b*(b-1))/2; }

__device__ __forceinline__ void cpa16(uint32_t smem_dst, const void* gsrc, int valid) {
    asm volatile("cp.async.cg.shared.global [%0], [%1], 16, %2;\n"
                 :: "r"(smem_dst), "l"(gsrc), "r"(valid ? 16 : 0));
}

// ---------------- zero -------------------------------------------------------
__global__ void k_zero() {
    int i = blockIdx.x*blockDim.x + threadIdx.x;
    if (i < 2*(NN+1)) ((int*)g_off)[i] = 0;
    if (i < 3) g_acc[i] = 0.0;
}

// ---------------- CSR build: count ------------------------------------------
__global__ void k_count(const int* __restrict__ d0, const int* __restrict__ d1) {
    int i = blockIdx.x*blockDim.x + threadIdx.x;
    if (i < EE)            atomicAdd(&g_off[0][d0[i]+1], 1);
    else if (i < 2*EE)     atomicAdd(&g_off[1][d1[i-EE]+1], 1);
}

// ---------------- CSR build: scan (1 block, 512 threads) ---------------------
__global__ void k_scan() {
    __shared__ int part[512];
    int tid = threadIdx.x;
    const int TOT = NN+1;
    const int CH  = (TOT + 511)/512;   // 20
    for (int g = 0; g < 2; g++) {
        int s = tid*CH, e = min(s+CH, TOT);
        int sum = 0;
        for (int i = s; i < e; i++) sum += g_off[g][i];
        part[tid] = sum;
        __syncthreads();
        if (tid == 0) {
            int run = 0;
            for (int i = 0; i < 512; i++) { int v = part[i]; part[i] = run; run += v; }
        }
        __syncthreads();
        int run = part[tid];
        for (int i = s; i < e; i++) {
            run += g_off[g][i];
            g_off[g][i] = run;
            if (i < NN) g_cur[g][i] = run;
        }
        __syncthreads();
    }
}

// ---------------- CSR build: fill ---------------------------------------------
__global__ void k_fill(const int* __restrict__ s0, const int* __restrict__ d0,
                       const float* __restrict__ v0,
                       const int* __restrict__ s1, const int* __restrict__ d1,
                       const float* __restrict__ v1) {
    int i = blockIdx.x*blockDim.x + threadIdx.x;
    if (i < EE) {
        int p = atomicAdd(&g_cur[0][d0[i]], 1);
        g_ssrc[0][p] = s0[i]; g_sval[0][p] = v0[i];
    } else if (i < 2*EE) {
        int j = i - EE;
        int p = atomicAdd(&g_cur[1][d1[j]], 1);
        g_ssrc[1][p] = s1[j]; g_sval[1][p] = v1[j];
    }
}

// ---------------- sup = x @ W + b   (tiled 128x128, 8x8 microtile) -----------
__global__ __launch_bounds__(256)
void k_sup(const float* __restrict__ x0, const float* __restrict__ W0, const float* __restrict__ b0,
           const float* __restrict__ x1, const float* __restrict__ W1, const float* __restrict__ b1) {
    int g = blockIdx.z;
    const float* x = g ? x1 : x0;
    const float* W = g ? W1 : W0;
    const float* b = g ? b1 : b0;
    float* sup = g_sup[g];

    __shared__ float As[32][128];
    __shared__ float Bs[32][128];
    int tid = threadIdx.x;
    int tx = tid & 15, ty = tid >> 4;
    int rb = blockIdx.x * 128;

    float acc[8][8];
#pragma unroll
    for (int i = 0; i < 8; i++)
#pragma unroll
        for (int j = 0; j < 8; j++) acc[i][j] = 0.f;

    for (int kc = 0; kc < DIN; kc += 32) {
#pragma unroll
        for (int p = 0; p < 4; p++) {               // A transpose load
            int idx = p*256 + tid;
            int row = idx & 127;
            int k0  = (idx >> 7) * 4;
            int gr  = rb + row;
            float4 v = make_float4(0.f,0.f,0.f,0.f);
            if (gr < NN) v = *(const float4*)(x + (size_t)gr*DIN + kc + k0);
            As[k0+0][row] = v.x; As[k0+1][row] = v.y;
            As[k0+2][row] = v.z; As[k0+3][row] = v.w;
        }
#pragma unroll
        for (int p = 0; p < 4; p++) {               // W direct load
            int idx = p*256 + tid;
            int kk  = idx >> 5;
            int c4  = (idx & 31) * 4;
            float4 v = *(const float4*)(W + (size_t)(kc+kk)*HIDN + c4);
            *(float4*)&Bs[kk][c4] = v;
        }
        __syncthreads();
#pragma unroll
        for (int k = 0; k < 32; k++) {
            float4 a0 = *(float4*)&As[k][ty*4];
            float4 a1 = *(float4*)&As[k][64 + ty*4];
            float4 c0 = *(float4*)&Bs[k][tx*4];
            float4 c1 = *(float4*)&Bs[k][64 + tx*4];
            float a[8] = {a0.x,a0.y,a0.z,a0.w,a1.x,a1.y,a1.z,a1.w};
            float c[8] = {c0.x,c0.y,c0.z,c0.w,c1.x,c1.y,c1.z,c1.w};
#pragma unroll
            for (int i = 0; i < 8; i++)
#pragma unroll
                for (int j = 0; j < 8; j++) acc[i][j] = fmaf(a[i], c[j], acc[i][j]);
        }
        __syncthreads();
    }
    float4 bv0 = *(const float4*)(b + tx*4);
    float4 bv1 = *(const float4*)(b + 64 + tx*4);
    float bb[8] = {bv0.x,bv0.y,bv0.z,bv0.w,bv1.x,bv1.y,bv1.z,bv1.w};
#pragma unroll
    for (int i = 0; i < 8; i++) {
        int r  = (i < 4) ? (ty*4 + i) : (64 + ty*4 + (i-4));
        int gr = rb + r;
        if (gr < NN) {
            float4 o0 = make_float4(acc[i][0]+bb[0], acc[i][1]+bb[1],
                                    acc[i][2]+bb[2], acc[i][3]+bb[3]);
            float4 o1 = make_float4(acc[i][4]+bb[4], acc[i][5]+bb[5],
                                    acc[i][6]+bb[6], acc[i][7]+bb[7]);
            *(float4*)(sup + (size_t)gr*HIDN + tx*4)      = o0;
            *(float4*)(sup + (size_t)gr*HIDN + 64 + tx*4) = o1;
        }
    }
}

// ---------------- aggregate + l2norm -> x_all (d_out) + fused bf16 cast ------
__global__ __launch_bounds__(128)
void k_agg(float* __restrict__ out) {
    int n   = blockIdx.x;
    int g   = blockIdx.y;
    int tid = threadIdx.x;              // dim 0..127
    const float* sup = g_sup[g];
    __shared__ int   ss[128];
    __shared__ float sv[128];
    float acc = 0.f;
    int s0 = g_off[g][n], s1 = g_off[g][n+1];
    for (int base = s0; base < s1; base += 128) {
        int cnt = min(128, s1 - base);
        __syncthreads();
        if (tid < cnt) { ss[tid] = g_ssrc[g][base+tid]; sv[tid] = g_sval[g][base+tid]; }
        __syncthreads();
#pragma unroll 4
        for (int q = 0; q < cnt; q++)
            acc = fmaf(sup[(size_t)ss[q]*HIDN + tid], sv[q], acc);
    }
    float sq = acc*acc;
#pragma unroll
    for (int o = 16; o; o >>= 1) sq += __shfl_xor_sync(0xffffffffu, sq, o);
    __shared__ float wsum[4];
    if ((tid & 31) == 0) wsum[tid>>5] = sq;
    __syncthreads();
    float tot = wsum[0] + wsum[1] + wsum[2] + wsum[3];
    float v = acc / sqrtf(tot);
    out[(size_t)n*DALL + g*HIDN + tid] = v;

    // fused bf16 cast of xn = v / sqrt(2)  (screening operand)
    g_xcat[(size_t)n*KBF + g*128 + tid] =
        __float2bfloat16_rn(v * 0.70710678118654752440f);
}

// ---------------- neg_s[i] = cos(x_all[i], x_all[neg_row[i]]) ----------------
__global__ __launch_bounds__(128)
void k_negs(const float* __restrict__ xall, const int* __restrict__ negrow) {
    int w    = (blockIdx.x*blockDim.x + threadIdx.x) >> 5;
    int lane = threadIdx.x & 31;
    if (w >= NN) return;
    int j = negrow[w];
    const float4* a = (const float4*)(xall + (size_t)w*DALL);
    const float4* b = (const float4*)(xall + (size_t)j*DALL);
    float s = 0.f;
#pragma unroll
    for (int q = lane; q < 64; q += 32) {
        float4 av = a[q], bv = b[q];
        s += av.x*bv.x + av.y*bv.y + av.z*bv.z + av.w*bv.w;
    }
#pragma unroll
    for (int o = 16; o; o >>= 1) s += __shfl_xor_sync(0xffffffffu, s, o);
    if (lane == 0) g_negs[w] = 0.5f*s;   // norms are exactly sqrt(2)
}

// ================= MEGA kernel: bf16-screen GEMM ∥ loss_real ∥ lc ============
__global__ __launch_bounds__(256, 2)
void k_mega(const float* __restrict__ xall, const int* __restrict__ ts,
            const int* __restrict__ negidx, const int* __restrict__ na,
            const int* __restrict__ nbv, const int* __restrict__ nl) {
    // double-buffered tiles: 2 stages x (A 16KB + B 16KB) = 64KB
    __shared__ __align__(128) char As[2][16384];
    __shared__ __align__(128) char Bs[2][16384];
    __shared__ double wred[8];
    __shared__ float  wr[8];

    int b    = blockIdx.x;
    int tid  = threadIdx.x;
    int lane = tid & 31;
    int wid  = tid >> 5;

    long long beforeP = (long long)b * NTILES / TOTALB;
    long long afterP  = (long long)(b+1) * NTILES / TOTALB;

    if (afterP > beforeP) {
        // ================= PSEUDO screen-GEMM role =================
        int t = (int)beforeP;
        float ff = (float)NB + 0.5f;
        int bi = (int)(ff - sqrtf(ff*ff - 2.0f*t));
        if (bi < 0) bi = 0; if (bi >= NB) bi = NB-1;
        while (bi > 0 && tri_off(bi) > t) bi--;
        while (tri_off(bi+1) <= t) bi++;
        int bj = bi + (t - tri_off(bi));
        int rA = bi * 128, rB = bj * 128;

        int wm = (wid >> 2) * 64;     // warp row offset
        int wn = (wid & 3)  * 32;     // warp col offset

        float acc[4][4][4];
#pragma unroll
        for (int a = 0; a < 4; a++)
#pragma unroll
            for (int bq = 0; bq < 4; bq++)
#pragma unroll
                for (int c = 0; c < 4; c++) acc[a][bq][c] = 0.f;

        const char* xbytes = (const char*)g_xcat;   // 512 B per row

        int r0 = tid >> 3;                 // rows r0, r0+32, r0+64, r0+96
        int cb = (tid & 7) * 16;           // byte col within 128B chunk row

        // prefetch chunk 0 -> stage 0
        {
            uint32_t a0 = (uint32_t)__cvta_generic_to_shared(As[0]);
            uint32_t b0 = (uint32_t)__cvta_generic_to_shared(Bs[0]);
#pragma unroll
            for (int p = 0; p < 4; p++) {
                int row = r0 + p*32;
                int sw  = row*128 + (cb ^ ((row & 7) * 16));
                int ga = rA + row, gb = rB + row;
                cpa16(a0 + sw, xbytes + (size_t)min(ga, NN-1)*512 + cb, ga < NN);
                cpa16(b0 + sw, xbytes + (size_t)min(gb, NN-1)*512 + cb, gb < NN);
            }
            asm volatile("cp.async.commit_group;\n");
        }

        for (int c = 0; c < 4; c++) {      // 4 chunks of 64 bf16 (K=256)
            if (c < 3) {
                int st = (c+1) & 1;
                uint32_t a0 = (uint32_t)__cvta_generic_to_shared(As[st]);
                uint32_t b0 = (uint32_t)__cvta_generic_to_shared(Bs[st]);
#pragma unroll
                for (int p = 0; p < 4; p++) {
                    int row = r0 + p*32;
                    int sw  = row*128 + (cb ^ ((row & 7) * 16));
                    int ga = rA + row, gb = rB + row;
                    const char* srcA = xbytes + (size_t)min(ga, NN-1)*512 + (c+1)*128 + cb;
                    const char* srcB = xbytes + (size_t)min(gb, NN-1)*512 + (c+1)*128 + cb;
                    cpa16(a0 + sw, srcA, ga < NN);
                    cpa16(b0 + sw, srcB, gb < NN);
                }
                asm volatile("cp.async.commit_group;\n");
                asm volatile("cp.async.wait_group 1;\n");
            } else {
                asm volatile("cp.async.wait_group 0;\n");
            }
            __syncthreads();

            int st = c & 1;
            const char* Ab = As[st];
            const char* Bb = Bs[st];
#pragma unroll
            for (int ks = 0; ks < 4; ks++) {
                uint32_t afr[4][4];
                uint32_t bfr[2][4];
                int cbk = ks*32 + (lane >> 4)*16;
#pragma unroll
                for (int mb = 0; mb < 4; mb++) {
                    int row = wm + mb*16 + (lane & 15);
                    uint32_t sa = (uint32_t)__cvta_generic_to_shared(
                                      Ab + row*128 + (cbk ^ ((row & 7) * 16)));
                    asm volatile("ldmatrix.sync.aligned.m8n8.x4.shared.b16 {%0,%1,%2,%3}, [%4];"
                        : "=r"(afr[mb][0]), "=r"(afr[mb][1]), "=r"(afr[mb][2]), "=r"(afr[mb][3])
                        : "r"(sa));
                }
#pragma unroll
                for (int nb2 = 0; nb2 < 2; nb2++) {
                    int row = wn + nb2*16 + (lane & 15);
                    uint32_t sb = (uint32_t)__cvta_generic_to_shared(
                                      Bb + row*128 + (cbk ^ ((row & 7) * 16)));
                    asm volatile("ldmatrix.sync.aligned.m8n8.x4.shared.b16 {%0,%1,%2,%3}, [%4];"
                        : "=r"(bfr[nb2][0]), "=r"(bfr[nb2][1]), "=r"(bfr[nb2][2]), "=r"(bfr[nb2][3])
                        : "r"(sb));
                }
#pragma unroll
                for (int mb = 0; mb < 4; mb++)
#pragma unroll
                    for (int nb = 0; nb < 4; nb++) {
                        int h = nb >> 1, o = nb & 1;
                        asm volatile(
                            "mma.sync.aligned.m16n8k16.row.col.f32.bf16.bf16.f32 "
                            "{%0,%1,%2,%3}, {%4,%5,%6,%7}, {%8,%9}, {%0,%1,%2,%3};"
                            : "+f"(acc[mb][nb][0]), "+f"(acc[mb][nb][1]),
                              "+f"(acc[mb][nb][2]), "+f"(acc[mb][nb][3])
                            : "r"(afr[mb][0]), "r"(afr[mb][1]), "r"(afr[mb][2]), "r"(afr[mb][3]),
                              "r"(bfr[h][o]),  "r"(bfr[h][o+2]));
                    }
            }
            __syncthreads();
        }

        // epilogue: screen at 0.945 (covers worst-case bf16 error 2^-8),
        // exact fp32 recompute for the rare candidates, exact mask + loss.
        float lsum = 0.f;
#pragma unroll
        for (int mb = 0; mb < 4; mb++) {
            int rr0 = rA + wm + mb*16 + (lane >> 2);
#pragma unroll
            for (int nb = 0; nb < 4; nb++) {
                int c0 = rB + wn + nb*8 + (lane & 3)*2;
#pragma unroll
                for (int e = 0; e < 4; e++) {
                    int gi = rr0 + (e >= 2 ? 8 : 0);
                    int gj = c0 + (e & 1);
                    float s = acc[mb][nb][e];
                    if (gj > gi && gj < NN && gi < NN && s > 0.945f) {
                        // exact fp32 dot of x_all rows (norms are exactly sqrt(2))
                        const float4* av = (const float4*)(xall + (size_t)gi*DALL);
                        const float4* bv = (const float4*)(xall + (size_t)gj*DALL);
                        float d = 0.f;
#pragma unroll
                        for (int q = 0; q < 64; q++) {
                            float4 x = av[q], y = bv[q];
                            d += x.x*y.x + x.y*y.y + x.z*y.z + x.w*y.w;
                        }
                        float se = 0.5f * d;
                        if (se > 0.95f) {
                            float u = (se - 0.1f) * (1.0f/0.9f);
                            lsum += (u*u) * log1pf(expf(g_negs[gi] - se));
                        }
                    }
                }
            }
        }
        float v = lsum;
#pragma unroll
        for (int o = 16; o; o >>= 1) v += __shfl_xor_sync(0xffffffffu, v, o);
        if (lane == 0) wred[wid] = (double)v;
        __syncthreads();
        if (tid == 0) {
            double s = 0;
#pragma unroll
            for (int q = 0; q < 8; q++) s += wred[q];
            if (s != 0.0) atomicAdd(&g_acc[1], s);
        }
        return;
    }

    // ----- non-pseudo: split into lc / real by second Bresenham spread -----
    long long r = b - beforeP;
    const long long NONP = (long long)NRB + NLB;
    long long beforeL = r * NLB / NONP;
    long long afterL  = (r+1) * NLB / NONP;

    if (afterL > beforeL) {
        // ================= LC role: 8 pairs, 1 per warp =================
        int pid = (int)beforeL * 8 + wid;
        float term = 0.f;
        {
            int ia = na[pid], ib = nbv[pid];
            const float4* a = (const float4*)(xall + (size_t)ia*DALL);
            const float4* bb = (const float4*)(xall + (size_t)ib*DALL);
            float s = 0.f;
#pragma unroll
            for (int q = lane; q < 64; q += 32) {
                float4 av = a[q], bv = bb[q];
                s += av.x*bv.x + av.y*bv.y + av.z*bv.z + av.w*bv.w;
            }
#pragma unroll
            for (int o = 16; o; o >>= 1) s += __shfl_xor_sync(0xffffffffu, s, o);
            if (lane == 0) {
                float sim = 0.5f*s;
                float z   = sim * 2.0f;               // sim / TAU0
                float ls  = (z >= 0.f) ? -log1pf(expf(-z)) : (z - log1pf(expf(z)));
                int   L   = nl[pid];
                term = ldexpf(1.0f, -(L+1)) * ls;     // GAMMA^(L+1) = 0.5^(L+1)
            }
        }
        if (lane == 0) wr[wid] = term;
        __syncthreads();
        if (tid == 0) {
            double s = 0;
#pragma unroll
            for (int q = 0; q < 8; q++) s += (double)wr[q];
            atomicAdd(&g_acc[2], s);
        }
    } else {
        // ================= REAL role: 8 pairs, 1 per warp =================
        int pid = (int)(r - beforeL) * 8 + wid;
        float term = 0.f;
        {
            int t0 = ts[2*pid], t1 = ts[2*pid+1], tn = negidx[pid];
            const float4* rs = (const float4*)(xall + (size_t)t0*DALL);
            const float4* re = (const float4*)(xall + (size_t)t1*DALL);
            const float4* ng = (const float4*)(xall + (size_t)tn*DALL);
            float ps = 0.f, ns = 0.f;
#pragma unroll
            for (int q = lane; q < 64; q += 32) {
                float4 rv = rs[q], e = re[q], n = ng[q];
                ps += rv.x*e.x + rv.y*e.y + rv.z*e.z + rv.w*e.w;
                ns += rv.x*n.x + rv.y*n.y + rv.z*n.z + rv.w*n.w;
            }
#pragma unroll
            for (int o = 16; o; o >>= 1) {
                ps += __shfl_xor_sync(0xffffffffu, ps, o);
                ns += __shfl_xor_sync(0xffffffffu, ns, o);
            }
            if (lane == 0) {
                float pos = 0.5f*ps, neg = 0.5f*ns;
                float u = (pos - 0.1f) * (1.0f/0.9f);
                term = (u*u) * log1pf(expf(neg - pos));
            }
        }
        if (lane == 0) wr[wid] = term;
        __syncthreads();
        if (tid == 0) {
            double s = 0;
#pragma unroll
            for (int q = 0; q < 8; q++) s += (double)wr[q];
            atomicAdd(&g_acc[0], s);
        }
    }
}

// ---------------- finalize ------------------------------------------------------
__global__ void k_final(float* out, int loss_idx) {
    double lc   = -g_acc[2] / (double)PP;
    double loss = g_acc[0] + g_acc[1] + 1.0 * lc;   // LAMBDA1 = 1
    out[loss_idx] = (float)loss;
}

// ---------------- launch ---------------------------------------------------------
extern "C" void kernel_launch(void* const* d_in, const int* in_sizes, int n_in,
                              void* d_out, int out_size) {
    const float* x0  = (const float*)d_in[0];
    const float* x1  = (const float*)d_in[1];
    const int*   a0s = (const int*)d_in[2];
    const int*   a0d = (const int*)d_in[3];
    const float* a0v = (const float*)d_in[4];
    const int*   a1s = (const int*)d_in[5];
    const int*   a1d = (const int*)d_in[6];
    const float* a1v = (const float*)d_in[7];
    const int*   ts  = (const int*)d_in[8];
    const int*   ngi = (const int*)d_in[9];
    const int*   ngr = (const int*)d_in[10];
    const int*   na  = (const int*)d_in[11];
    const int*   nb  = (const int*)d_in[12];
    const int*   nl  = (const int*)d_in[13];
    const float* W0  = (const float*)d_in[14];
    const float* b0  = (const float*)d_in[15];
    const float* W1  = (const float*)d_in[16];
    const float* b1  = (const float*)d_in[17];
    float* out = (float*)d_out;

    k_zero <<<(2*(NN+1)+255)/256, 256>>>();
    k_count<<<(2*EE+255)/256, 256>>>(a0d, a1d);
    k_scan <<<1, 512>>>();
    k_fill <<<(2*EE+255)/256, 256>>>(a0s, a0d, a0v, a1s, a1d, a1v);
    k_sup  <<<dim3(NB,1,2), 256>>>(x0, W0, b0, x1, W1, b1);
    k_agg  <<<dim3(NN,2), 128>>>(out);
    k_negs <<<NN/4, 128>>>(out, ngr);
    k_mega <<<TOTALB, 256>>>(out, ts, ngi, na, nb, nl);
    k_final<<<1, 1>>>(out, out_size - 1);
}